// round 1
// baseline (speedup 1.0000x reference)
#include <cuda_runtime.h>
#include <cuda_bf16.h>

// Problem constants
#define BATCH   8
#define NW      64
#define NTOK    64          // WH*WW
#define DIM     512
#define HEADS   16
#define HD      32
#define C3      1536        // 3*DIM
#define MROWS   (BATCH*NW*NTOK)   // 32768
#define LN100   4.605170185988092f

// Scratch (allocation-free rule: __device__ globals)
__device__ float g_qkv[(long)MROWS * C3];     // 192 MB
__device__ float g_att[(long)MROWS * DIM];    // 64 MB

// ---------------------------------------------------------------------------
// Tiled SGEMM: C[m,n] = sum_k A[m,k] * W[n,k] + bias(n)
// BM=BN=64, BK=32, 256 threads, 4x4 per thread.
// MODE 0: qkv bias (q_bias | 0 | v_bias), MODE 1: plain bias b0[n]
// ---------------------------------------------------------------------------
template<int N, int K, int MODE>
__global__ __launch_bounds__(256) void sgemm_kernel(
    const float* __restrict__ A, const float* __restrict__ W,
    const float* __restrict__ b0, const float* __restrict__ b1,
    float* __restrict__ C)
{
    __shared__ float As[32][65];
    __shared__ float Ws[32][65];

    const int t  = threadIdx.x;
    const int tx = t & 15;
    const int ty = t >> 4;
    const int rowBase = blockIdx.y * 64;
    const int colBase = blockIdx.x * 64;

    float acc[4][4] = {};

    for (int kt = 0; kt < K; kt += 32) {
        #pragma unroll
        for (int it = 0; it < 2; ++it) {
            int idx = t + it * 256;          // 0..511
            int r   = idx >> 3;              // 0..63
            int c   = (idx & 7) << 2;        // 0..28 step 4
            float4 av = *(const float4*)(A + (long)(rowBase + r) * K + kt + c);
            As[c+0][r] = av.x; As[c+1][r] = av.y; As[c+2][r] = av.z; As[c+3][r] = av.w;
            float4 wv = *(const float4*)(W + (long)(colBase + r) * K + kt + c);
            Ws[c+0][r] = wv.x; Ws[c+1][r] = wv.y; Ws[c+2][r] = wv.z; Ws[c+3][r] = wv.w;
        }
        __syncthreads();

        #pragma unroll
        for (int k = 0; k < 32; ++k) {
            float a[4], w[4];
            #pragma unroll
            for (int i = 0; i < 4; ++i) a[i] = As[k][ty*4 + i];
            #pragma unroll
            for (int j = 0; j < 4; ++j) w[j] = Ws[k][tx*4 + j];
            #pragma unroll
            for (int i = 0; i < 4; ++i)
                #pragma unroll
                for (int j = 0; j < 4; ++j)
                    acc[i][j] = fmaf(a[i], w[j], acc[i][j]);
        }
        __syncthreads();
    }

    #pragma unroll
    for (int i = 0; i < 4; ++i) {
        int row = rowBase + ty*4 + i;
        #pragma unroll
        for (int j = 0; j < 4; ++j) {
            int col = colBase + tx*4 + j;
            float bias;
            if (MODE == 0) {
                bias = (col < 512) ? b0[col] : ((col < 1024) ? 0.0f : b1[col - 1024]);
            } else {
                bias = b0[col];
            }
            C[(long)row * N + col] = acc[i][j] + bias;
        }
    }
}

// ---------------------------------------------------------------------------
// Per-window cosine attention with axial RoPE.
// Grid: (NW, HEADS, BATCH), 256 threads.
// ---------------------------------------------------------------------------
__global__ __launch_bounds__(256) void attn_kernel(
    const float* __restrict__ logit_scale, float* __restrict__ out)
{
    const int w = blockIdx.x;
    const int h = blockIdx.y;
    const int b = blockIdx.z;
    const int t = threadIdx.x;

    __shared__ __align__(16) float sq[64][33];
    __shared__ __align__(16) float sk[64][33];
    __shared__ __align__(16) float sv[64][32];
    __shared__ __align__(16) float sp[64][65];

    const long rowm = (long)(b * NW + w) * NTOK;         // first row of window
    const float* qp = g_qkv + rowm * C3 + h * HD;
    const float* kp = qp + 512;
    const float* vp = qp + 1024;

    // Load q, k, v tiles (each 64x32)
    #pragma unroll
    for (int it = 0; it < 2; ++it) {
        int idx = t + it * 256;         // 0..511 float4 slots
        int r   = idx >> 3;
        int c   = (idx & 7) << 2;
        float4 qv = *(const float4*)(qp + (long)r * C3 + c);
        float4 kv = *(const float4*)(kp + (long)r * C3 + c);
        float4 vv = *(const float4*)(vp + (long)r * C3 + c);
        sq[r][c+0]=qv.x; sq[r][c+1]=qv.y; sq[r][c+2]=qv.z; sq[r][c+3]=qv.w;
        sk[r][c+0]=kv.x; sk[r][c+1]=kv.y; sk[r][c+2]=kv.z; sk[r][c+3]=kv.w;
        *(float4*)&sv[r][c] = vv;
    }
    __syncthreads();

    // Normalize + scale + RoPE. Threads 0..63: q rows, 64..127: k rows.
    if (t < 128) {
        const int r = t & 63;
        float* row = (t < 64) ? &sq[r][0] : &sk[r][0];

        float ss = 0.f;
        #pragma unroll
        for (int d = 0; d < 32; ++d) { float x = row[d]; ss += x * x; }
        float scale = 1.0f / fmaxf(sqrtf(ss), 1e-12f);
        if (t < 64) {
            // fold logit scale and 1/sqrt(HD) into q
            scale *= expf(fmaxf(logit_scale[h], LN100)) * 0.17677669529663687f;
        }

        // inv[j] = 10000^(-j/8), exact constants
        const float inv_tab[8] = {
            1.0f, 0.31622776601683794f, 0.1f, 0.03162277660168379f,
            0.01f, 0.0031622776601683794f, 0.001f, 0.00031622776601683794f };

        const int ih = r >> 3, iw = r & 7;
        #pragma unroll
        for (int p = 0; p < 16; ++p) {
            const int d = 2 * p;
            const float pos = (p < 8) ? (float)ih : (float)iw;
            const float f = pos * inv_tab[p & 7];
            float sf, cf;
            sincosf(f, &sf, &cf);
            const float x0 = row[d] * scale, x1 = row[d + 1] * scale;
            row[d]     = x0 * cf - x1 * sf;
            row[d + 1] = x1 * cf + x0 * sf;
        }
    }
    __syncthreads();

    // Scores + softmax: 4 lanes per row, 16 columns each.
    {
        const int r = t >> 2;
        const int cb = (t & 3) * 16;
        float sc[16];
        #pragma unroll
        for (int i = 0; i < 16; ++i) {
            const int c = cb + i;
            float acc = 0.f;
            #pragma unroll
            for (int d = 0; d < 32; ++d) acc = fmaf(sq[r][d], sk[c][d], acc);
            sc[i] = acc;
        }
        float mx = sc[0];
        #pragma unroll
        for (int i = 1; i < 16; ++i) mx = fmaxf(mx, sc[i]);
        mx = fmaxf(mx, __shfl_xor_sync(0xffffffff, mx, 1));
        mx = fmaxf(mx, __shfl_xor_sync(0xffffffff, mx, 2));
        float sum = 0.f;
        #pragma unroll
        for (int i = 0; i < 16; ++i) { sc[i] = expf(sc[i] - mx); sum += sc[i]; }
        sum += __shfl_xor_sync(0xffffffff, sum, 1);
        sum += __shfl_xor_sync(0xffffffff, sum, 2);
        const float rinv = 1.0f / sum;
        #pragma unroll
        for (int i = 0; i < 16; ++i) sp[r][cb + i] = sc[i] * rinv;
    }
    __syncthreads();

    // out = P @ V : thread (d = t&31, q0 = t>>5), 8 rows each
    {
        const int d  = t & 31;
        const int q0 = t >> 5;
        #pragma unroll
        for (int j = 0; j < 8; ++j) {
            const int qr = q0 * 8 + j;
            float acc = 0.f;
            #pragma unroll
            for (int k = 0; k < 64; ++k) acc = fmaf(sp[qr][k], sv[k][d], acc);
            out[(rowm + qr) * DIM + h * HD + d] = acc;
        }
    }
}

// ---------------------------------------------------------------------------
extern "C" void kernel_launch(void* const* d_in, const int* in_sizes, int n_in,
                              void* d_out, int out_size)
{
    const float* x           = (const float*)d_in[0];   // (8,64,64,512)
    const float* qkv_weight  = (const float*)d_in[1];   // (1536,512)
    const float* q_bias      = (const float*)d_in[2];   // (512)
    const float* v_bias      = (const float*)d_in[3];   // (512)
    const float* logit_scale = (const float*)d_in[4];   // (16)
    const float* proj_weight = (const float*)d_in[5];   // (512,512)
    const float* proj_bias   = (const float*)d_in[6];   // (512)
    float* outp = (float*)d_out;

    float* qkv; cudaGetSymbolAddress((void**)&qkv, g_qkv);
    float* att; cudaGetSymbolAddress((void**)&att, g_att);

    // 1) qkv = x @ Wqkv^T + [q_bias | 0 | v_bias]
    sgemm_kernel<C3, DIM, 0><<<dim3(C3/64, MROWS/64), 256>>>(
        x, qkv_weight, q_bias, v_bias, qkv);

    // 2) windowed cosine attention + RoPE
    attn_kernel<<<dim3(NW, HEADS, BATCH), 256>>>(logit_scale, att);

    // 3) out = att @ Wproj^T + proj_bias
    sgemm_kernel<DIM, DIM, 1><<<dim3(DIM/64, MROWS/64), 256>>>(
        att, proj_weight, proj_bias, nullptr, outp);
}

// round 2
// speedup vs baseline: 2.8981x; 2.8981x over previous
#include <cuda_runtime.h>
#include <cuda_bf16.h>
#include <cstdint>

// Problem constants
#define BATCH   8
#define NW      64
#define NTOK    64          // WH*WW
#define DIM     512
#define HEADS   16
#define HD      32
#define C3      1536        // 3*DIM
#define MROWS   (BATCH*NW*NTOK)   // 32768
#define LN100   4.605170185988092f

// Scratch (allocation-free rule: __device__ globals)
__device__ float g_qkv[(long)MROWS * C3];     // 192 MB
__device__ float g_att[(long)MROWS * DIM];    // 64 MB

__device__ __forceinline__ unsigned f2tf32(float x) {
    unsigned u;
    asm("cvt.rna.tf32.f32 %0, %1;" : "=r"(u) : "f"(x));
    return u;
}

__device__ __forceinline__ void mma_tf32(float c[4], const unsigned a[4], const unsigned b[2]) {
    asm volatile(
        "mma.sync.aligned.m16n8k8.row.col.f32.tf32.tf32.f32 "
        "{%0,%1,%2,%3}, {%4,%5,%6,%7}, {%8,%9}, {%0,%1,%2,%3};"
        : "+f"(c[0]), "+f"(c[1]), "+f"(c[2]), "+f"(c[3])
        : "r"(a[0]), "r"(a[1]), "r"(a[2]), "r"(a[3]), "r"(b[0]), "r"(b[1]));
}

// ---------------------------------------------------------------------------
// TF32 tensor-core GEMM: C[m,n] = sum_k A[m,k] * W[n,k] + bias(n)
// CTA tile 128x128, BK=32, 256 threads = 8 warps in 2(M) x 4(N),
// warp tile 64x32 via m16n8k8 (4 m-tiles x 4 n-tiles).
// MODE 0: qkv bias (q_bias | 0 | v_bias), MODE 1: plain bias b0[n]
// ---------------------------------------------------------------------------
template<int N, int K, int MODE>
__global__ __launch_bounds__(256) void mma_gemm(
    const float* __restrict__ A, const float* __restrict__ W,
    const float* __restrict__ b0, const float* __restrict__ b1,
    float* __restrict__ C)
{
    __shared__ unsigned As[128][36];   // [m][k] tf32 bits
    __shared__ unsigned Bs[128][36];   // [n][k] tf32 bits

    const int t    = threadIdx.x;
    const int warp = t >> 5;
    const int lane = t & 31;
    const int g    = lane >> 2;     // groupID 0..7
    const int t4   = lane & 3;      // 0..3
    const int wm   = warp >> 2;     // 0..1 (M)
    const int wn   = warp & 3;      // 0..3 (N)

    const int rowBase = blockIdx.y * 128;
    const int colBase = blockIdx.x * 128;

    // gmem staging indices: 256 threads, row = pass*32 + (t>>3), col = (t&7)*4
    const int ldr = t >> 3;
    const int ldc = (t & 7) * 4;

    float acc[4][4][4] = {};   // [mt][nt][4]
    float4 aReg[4], bReg[4];

    // prologue: load tile kt=0
    #pragma unroll
    for (int p = 0; p < 4; ++p) {
        aReg[p] = *(const float4*)(A + (long)(rowBase + p*32 + ldr) * K + ldc);
        bReg[p] = *(const float4*)(W + (long)(colBase + p*32 + ldr) * K + ldc);
    }
    #pragma unroll
    for (int p = 0; p < 4; ++p) {
        As[p*32+ldr][ldc+0] = f2tf32(aReg[p].x);
        As[p*32+ldr][ldc+1] = f2tf32(aReg[p].y);
        As[p*32+ldr][ldc+2] = f2tf32(aReg[p].z);
        As[p*32+ldr][ldc+3] = f2tf32(aReg[p].w);
        Bs[p*32+ldr][ldc+0] = f2tf32(bReg[p].x);
        Bs[p*32+ldr][ldc+1] = f2tf32(bReg[p].y);
        Bs[p*32+ldr][ldc+2] = f2tf32(bReg[p].z);
        Bs[p*32+ldr][ldc+3] = f2tf32(bReg[p].w);
    }
    __syncthreads();

    for (int kt = 0; kt < K; kt += 32) {
        const bool more = (kt + 32) < K;
        if (more) {
            #pragma unroll
            for (int p = 0; p < 4; ++p) {
                aReg[p] = *(const float4*)(A + (long)(rowBase + p*32 + ldr) * K + kt + 32 + ldc);
                bReg[p] = *(const float4*)(W + (long)(colBase + p*32 + ldr) * K + kt + 32 + ldc);
            }
        }

        // compute 4 k8 steps over the smem tile
        #pragma unroll
        for (int ks = 0; ks < 4; ++ks) {
            const int k0 = ks * 8;
            unsigned af[4][4], bf[4][2];
            #pragma unroll
            for (int mt = 0; mt < 4; ++mt) {
                const int r0 = wm*64 + mt*16 + g;
                af[mt][0] = As[r0    ][k0 + t4    ];
                af[mt][1] = As[r0 + 8][k0 + t4    ];
                af[mt][2] = As[r0    ][k0 + t4 + 4];
                af[mt][3] = As[r0 + 8][k0 + t4 + 4];
            }
            #pragma unroll
            for (int nt = 0; nt < 4; ++nt) {
                const int c0 = wn*32 + nt*8 + g;
                bf[nt][0] = Bs[c0][k0 + t4    ];
                bf[nt][1] = Bs[c0][k0 + t4 + 4];
            }
            #pragma unroll
            for (int mt = 0; mt < 4; ++mt)
                #pragma unroll
                for (int nt = 0; nt < 4; ++nt)
                    mma_tf32(acc[mt][nt], af[mt], bf[nt]);
        }

        if (more) {
            __syncthreads();
            #pragma unroll
            for (int p = 0; p < 4; ++p) {
                As[p*32+ldr][ldc+0] = f2tf32(aReg[p].x);
                As[p*32+ldr][ldc+1] = f2tf32(aReg[p].y);
                As[p*32+ldr][ldc+2] = f2tf32(aReg[p].z);
                As[p*32+ldr][ldc+3] = f2tf32(aReg[p].w);
                Bs[p*32+ldr][ldc+0] = f2tf32(bReg[p].x);
                Bs[p*32+ldr][ldc+1] = f2tf32(bReg[p].y);
                Bs[p*32+ldr][ldc+2] = f2tf32(bReg[p].z);
                Bs[p*32+ldr][ldc+3] = f2tf32(bReg[p].w);
            }
            __syncthreads();
        }
    }

    // epilogue with bias
    #pragma unroll
    for (int mt = 0; mt < 4; ++mt) {
        #pragma unroll
        for (int nt = 0; nt < 4; ++nt) {
            const int row0 = rowBase + wm*64 + mt*16 + g;
            const int col0 = colBase + wn*32 + nt*8 + t4*2;
            float bias0, bias1;
            if (MODE == 0) {
                bias0 = (col0 < 512) ? b0[col0] : ((col0 < 1024) ? 0.0f : b1[col0 - 1024]);
                const int c1 = col0 + 1;
                bias1 = (c1 < 512) ? b0[c1] : ((c1 < 1024) ? 0.0f : b1[c1 - 1024]);
            } else {
                bias0 = b0[col0];
                bias1 = b0[col0 + 1];
            }
            C[(long)row0 * N + col0    ] = acc[mt][nt][0] + bias0;
            C[(long)row0 * N + col0 + 1] = acc[mt][nt][1] + bias1;
            C[(long)(row0+8) * N + col0    ] = acc[mt][nt][2] + bias0;
            C[(long)(row0+8) * N + col0 + 1] = acc[mt][nt][3] + bias1;
        }
    }
}

// ---------------------------------------------------------------------------
// Per-window cosine attention with axial RoPE.
// Grid: (NW, HEADS, BATCH), 256 threads.
// ---------------------------------------------------------------------------
__global__ __launch_bounds__(256) void attn_kernel(
    const float* __restrict__ logit_scale, float* __restrict__ out)
{
    const int w = blockIdx.x;
    const int h = blockIdx.y;
    const int b = blockIdx.z;
    const int t = threadIdx.x;

    __shared__ __align__(16) float sq[64][33];
    __shared__ __align__(16) float sk[64][33];
    __shared__ __align__(16) float sv[64][32];
    __shared__ __align__(16) float sp[64][65];

    const long rowm = (long)(b * NW + w) * NTOK;         // first row of window
    const float* qp = g_qkv + rowm * C3 + h * HD;
    const float* kp = qp + 512;
    const float* vp = qp + 1024;

    // Load q, k, v tiles (each 64x32)
    #pragma unroll
    for (int it = 0; it < 2; ++it) {
        int idx = t + it * 256;         // 0..511 float4 slots
        int r   = idx >> 3;
        int c   = (idx & 7) << 2;
        float4 qv = *(const float4*)(qp + (long)r * C3 + c);
        float4 kv = *(const float4*)(kp + (long)r * C3 + c);
        float4 vv = *(const float4*)(vp + (long)r * C3 + c);
        sq[r][c+0]=qv.x; sq[r][c+1]=qv.y; sq[r][c+2]=qv.z; sq[r][c+3]=qv.w;
        sk[r][c+0]=kv.x; sk[r][c+1]=kv.y; sk[r][c+2]=kv.z; sk[r][c+3]=kv.w;
        *(float4*)&sv[r][c] = vv;
    }
    __syncthreads();

    // Normalize + scale + RoPE. Threads 0..63: q rows, 64..127: k rows.
    if (t < 128) {
        const int r = t & 63;
        float* row = (t < 64) ? &sq[r][0] : &sk[r][0];

        float ss = 0.f;
        #pragma unroll
        for (int d = 0; d < 32; ++d) { float x = row[d]; ss += x * x; }
        float scale = 1.0f / fmaxf(sqrtf(ss), 1e-12f);
        if (t < 64) {
            // fold logit scale and 1/sqrt(HD) into q
            scale *= expf(fmaxf(logit_scale[h], LN100)) * 0.17677669529663687f;
        }

        // inv[j] = 10000^(-j/8), exact constants
        const float inv_tab[8] = {
            1.0f, 0.31622776601683794f, 0.1f, 0.03162277660168379f,
            0.01f, 0.0031622776601683794f, 0.001f, 0.00031622776601683794f };

        const int ih = r >> 3, iw = r & 7;
        #pragma unroll
        for (int p = 0; p < 16; ++p) {
            const int d = 2 * p;
            const float pos = (p < 8) ? (float)ih : (float)iw;
            const float f = pos * inv_tab[p & 7];
            float sf, cf;
            sincosf(f, &sf, &cf);
            const float x0 = row[d] * scale, x1 = row[d + 1] * scale;
            row[d]     = x0 * cf - x1 * sf;
            row[d + 1] = x1 * cf + x0 * sf;
        }
    }
    __syncthreads();

    // Scores + softmax: 4 lanes per row, 16 columns each.
    {
        const int r = t >> 2;
        const int cb = (t & 3) * 16;
        float sc[16];
        #pragma unroll
        for (int i = 0; i < 16; ++i) {
            const int c = cb + i;
            float acc = 0.f;
            #pragma unroll
            for (int d = 0; d < 32; ++d) acc = fmaf(sq[r][d], sk[c][d], acc);
            sc[i] = acc;
        }
        float mx = sc[0];
        #pragma unroll
        for (int i = 1; i < 16; ++i) mx = fmaxf(mx, sc[i]);
        mx = fmaxf(mx, __shfl_xor_sync(0xffffffff, mx, 1));
        mx = fmaxf(mx, __shfl_xor_sync(0xffffffff, mx, 2));
        float sum = 0.f;
        #pragma unroll
        for (int i = 0; i < 16; ++i) { sc[i] = expf(sc[i] - mx); sum += sc[i]; }
        sum += __shfl_xor_sync(0xffffffff, sum, 1);
        sum += __shfl_xor_sync(0xffffffff, sum, 2);
        const float rinv = 1.0f / sum;
        #pragma unroll
        for (int i = 0; i < 16; ++i) sp[r][cb + i] = sc[i] * rinv;
    }
    __syncthreads();

    // out = P @ V : thread (d = t&31, q0 = t>>5), 8 rows each
    {
        const int d  = t & 31;
        const int q0 = t >> 5;
        #pragma unroll
        for (int j = 0; j < 8; ++j) {
            const int qr = q0 * 8 + j;
            float acc = 0.f;
            #pragma unroll
            for (int k = 0; k < 64; ++k) acc = fmaf(sp[qr][k], sv[k][d], acc);
            out[(rowm + qr) * DIM + h * HD + d] = acc;
        }
    }
}

// ---------------------------------------------------------------------------
extern "C" void kernel_launch(void* const* d_in, const int* in_sizes, int n_in,
                              void* d_out, int out_size)
{
    const float* x           = (const float*)d_in[0];   // (8,64,64,512)
    const float* qkv_weight  = (const float*)d_in[1];   // (1536,512)
    const float* q_bias      = (const float*)d_in[2];   // (512)
    const float* v_bias      = (const float*)d_in[3];   // (512)
    const float* logit_scale = (const float*)d_in[4];   // (16)
    const float* proj_weight = (const float*)d_in[5];   // (512,512)
    const float* proj_bias   = (const float*)d_in[6];   // (512)
    float* outp = (float*)d_out;

    float* qkv; cudaGetSymbolAddress((void**)&qkv, g_qkv);
    float* att; cudaGetSymbolAddress((void**)&att, g_att);

    // 1) qkv = x @ Wqkv^T + [q_bias | 0 | v_bias]   (M=32768, N=1536, K=512)
    mma_gemm<C3, DIM, 0><<<dim3(C3/128, MROWS/128), 256>>>(
        x, qkv_weight, q_bias, v_bias, qkv);

    // 2) windowed cosine attention + RoPE
    attn_kernel<<<dim3(NW, HEADS, BATCH), 256>>>(logit_scale, att);

    // 3) out = att @ Wproj^T + proj_bias            (M=32768, N=512, K=512)
    mma_gemm<DIM, DIM, 1><<<dim3(DIM/128, MROWS/128), 256>>>(
        att, proj_weight, proj_bias, nullptr, outp);
}

// round 3
// speedup vs baseline: 3.2130x; 1.1087x over previous
#include <cuda_runtime.h>
#include <cuda_bf16.h>
#include <cstdint>

// Problem constants
#define BATCH   8
#define NW      64
#define NTOK    64          // WH*WW
#define DIM     512
#define HEADS   16
#define HD      32
#define C3      1536        // 3*DIM
#define MROWS   (BATCH*NW*NTOK)   // 32768
#define LN100   4.605170185988092f

// Scratch (allocation-free rule: __device__ globals)
__device__ float g_qkv[(long)MROWS * C3];     // 192 MB
__device__ float g_att[(long)MROWS * DIM];    // 64 MB

__device__ __forceinline__ unsigned f2tf32(float x) {
    unsigned u;
    asm("cvt.rna.tf32.f32 %0, %1;" : "=r"(u) : "f"(x));
    return u;
}

__device__ __forceinline__ void mma_tf32(float c[4], const unsigned a[4], const unsigned b[2]) {
    asm volatile(
        "mma.sync.aligned.m16n8k8.row.col.f32.tf32.tf32.f32 "
        "{%0,%1,%2,%3}, {%4,%5,%6,%7}, {%8,%9}, {%0,%1,%2,%3};"
        : "+f"(c[0]), "+f"(c[1]), "+f"(c[2]), "+f"(c[3])
        : "r"(a[0]), "r"(a[1]), "r"(a[2]), "r"(a[3]), "r"(b[0]), "r"(b[1]));
}

// within an 8-wide k-group, put (k, k+4) adjacent: kk -> ((kk&3)<<1)|(kk>>2)
__device__ __forceinline__ int perm8(int kk) { return ((kk & 3) << 1) | (kk >> 2); }

// ---------------------------------------------------------------------------
// TF32 tensor-core GEMM: C[m,n] = sum_k A[m,k] * W[n,k] + bias(n)
// CTA 128x128, BK=32, 256 threads = 8 warps (2M x 4N), warp tile 64x32.
// Smem rows hold k in pair-permuted order so fragment loads are LDS.64.
// mma order identical to the R2 kernel -> bitwise identical results.
// ---------------------------------------------------------------------------
template<int N, int K, int MODE>
__global__ __launch_bounds__(256) void mma_gemm(
    const float* __restrict__ A, const float* __restrict__ W,
    const float* __restrict__ b0, const float* __restrict__ b1,
    float* __restrict__ C)
{
    __shared__ unsigned As[128][40];   // [m][perm(k)] tf32 bits
    __shared__ unsigned Bs[128][40];   // [n][perm(k)]

    const int t    = threadIdx.x;
    const int warp = t >> 5;
    const int lane = t & 31;
    const int g    = lane >> 2;
    const int t4   = lane & 3;
    const int wm   = warp >> 2;
    const int wn   = warp & 3;

    const int rowBase = blockIdx.y * 128;
    const int colBase = blockIdx.x * 128;

    // staging: thread t covers row (p*32 + t>>3), k-group (t&7)>>1, half (t&7)&1
    const int ldr  = t >> 3;
    const int j    = t & 7;
    const int g8   = j >> 1;
    const int kk0  = (j & 1) * 2;
    const int kOff = g8 * 8 + kk0;        // gmem k base (loads kOff,kOff+1 and +4,+5)
    const int sOff = g8 * 8 + kk0 * 2;    // smem word base (4 perm-contiguous slots)

    float acc[4][4][4] = {};
    float2 aU[4], aW[4], bU[4], bW[4];

    // prologue stage kt=0
    #pragma unroll
    for (int p = 0; p < 4; ++p) {
        const float* ap = A + (long)(rowBase + p*32 + ldr) * K + kOff;
        aU[p] = *(const float2*)ap;  aW[p] = *(const float2*)(ap + 4);
        const float* bp = W + (long)(colBase + p*32 + ldr) * K + kOff;
        bU[p] = *(const float2*)bp;  bW[p] = *(const float2*)(bp + 4);
    }
    #pragma unroll
    for (int p = 0; p < 4; ++p) {
        uint4 av = make_uint4(f2tf32(aU[p].x), f2tf32(aW[p].x), f2tf32(aU[p].y), f2tf32(aW[p].y));
        *(uint4*)&As[p*32 + ldr][sOff] = av;
        uint4 bv = make_uint4(f2tf32(bU[p].x), f2tf32(bW[p].x), f2tf32(bU[p].y), f2tf32(bW[p].y));
        *(uint4*)&Bs[p*32 + ldr][sOff] = bv;
    }
    __syncthreads();

    for (int kt = 0; kt < K; kt += 32) {
        const bool more = (kt + 32) < K;
        if (more) {
            #pragma unroll
            for (int p = 0; p < 4; ++p) {
                const float* ap = A + (long)(rowBase + p*32 + ldr) * K + kt + 32 + kOff;
                aU[p] = *(const float2*)ap;  aW[p] = *(const float2*)(ap + 4);
                const float* bp = W + (long)(colBase + p*32 + ldr) * K + kt + 32 + kOff;
                bU[p] = *(const float2*)bp;  bW[p] = *(const float2*)(bp + 4);
            }
        }

        #pragma unroll
        for (int ks = 0; ks < 4; ++ks) {
            const int ko = ks * 8 + 2 * t4;
            unsigned af[4][4], bf[4][2];
            #pragma unroll
            for (int mt = 0; mt < 4; ++mt) {
                const int r0 = wm*64 + mt*16 + g;
                uint2 x = *(const uint2*)&As[r0    ][ko];
                uint2 y = *(const uint2*)&As[r0 + 8][ko];
                af[mt][0] = x.x; af[mt][2] = x.y;
                af[mt][1] = y.x; af[mt][3] = y.y;
            }
            #pragma unroll
            for (int nt = 0; nt < 4; ++nt) {
                const int c0 = wn*32 + nt*8 + g;
                uint2 bb = *(const uint2*)&Bs[c0][ko];
                bf[nt][0] = bb.x; bf[nt][1] = bb.y;
            }
            #pragma unroll
            for (int mt = 0; mt < 4; ++mt)
                #pragma unroll
                for (int nt = 0; nt < 4; ++nt)
                    mma_tf32(acc[mt][nt], af[mt], bf[nt]);
        }

        if (more) {
            __syncthreads();
            #pragma unroll
            for (int p = 0; p < 4; ++p) {
                uint4 av = make_uint4(f2tf32(aU[p].x), f2tf32(aW[p].x), f2tf32(aU[p].y), f2tf32(aW[p].y));
                *(uint4*)&As[p*32 + ldr][sOff] = av;
                uint4 bv = make_uint4(f2tf32(bU[p].x), f2tf32(bW[p].x), f2tf32(bU[p].y), f2tf32(bW[p].y));
                *(uint4*)&Bs[p*32 + ldr][sOff] = bv;
            }
            __syncthreads();
        }
    }

    // epilogue with bias
    #pragma unroll
    for (int mt = 0; mt < 4; ++mt) {
        #pragma unroll
        for (int nt = 0; nt < 4; ++nt) {
            const int row0 = rowBase + wm*64 + mt*16 + g;
            const int col0 = colBase + wn*32 + nt*8 + t4*2;
            float bias0, bias1;
            if (MODE == 0) {
                bias0 = (col0 < 512) ? b0[col0] : ((col0 < 1024) ? 0.0f : b1[col0 - 1024]);
                const int c1 = col0 + 1;
                bias1 = (c1 < 512) ? b0[c1] : ((c1 < 1024) ? 0.0f : b1[c1 - 1024]);
            } else {
                bias0 = b0[col0];
                bias1 = b0[col0 + 1];
            }
            C[(long)row0 * N + col0    ] = acc[mt][nt][0] + bias0;
            C[(long)row0 * N + col0 + 1] = acc[mt][nt][1] + bias1;
            C[(long)(row0+8) * N + col0    ] = acc[mt][nt][2] + bias0;
            C[(long)(row0+8) * N + col0 + 1] = acc[mt][nt][3] + bias1;
        }
    }
}

// ---------------------------------------------------------------------------
// Per-window cosine attention with axial RoPE — tensor-core (3xTF32 = ~fp32).
// Grid: (NW, HEADS, BATCH), 256 threads = 8 warps (2M x 4N).
// ---------------------------------------------------------------------------
__global__ __launch_bounds__(256) void attn_kernel(
    const float* __restrict__ logit_scale, float* __restrict__ out)
{
    __shared__ float sq [64][40];   // q rows, k-perm layout (after phase 1b)
    __shared__ float sk [64][40];   // k rows, k-perm layout
    __shared__ float svT[32][72];   // V transposed: [d][perm(key)]
    __shared__ float sp [64][72];   // scores/probs: [q][perm(key)]

    const int w = blockIdx.x, h = blockIdx.y, b = blockIdx.z;
    const int t    = threadIdx.x;
    const int warp = t >> 5;
    const int lane = t & 31;
    const int g    = lane >> 2;
    const int t4   = lane & 3;
    const int wm   = warp >> 2;
    const int wn   = warp & 3;

    const long rowm = (long)(b * NW + w) * NTOK;
    const float* qp = g_qkv + rowm * C3 + h * HD;
    const float* kp = qp + 512;
    const float* vp = qp + 1024;

    // ---- Phase 1a: load q,k raw row-major; V transposed+permuted ----
    #pragma unroll
    for (int it = 0; it < 2; ++it) {
        int idx = t + it * 256;
        int r = idx >> 3, c = (idx & 7) * 4;
        *(float4*)&sq[r][c] = *(const float4*)(qp + (long)r * C3 + c);
        *(float4*)&sk[r][c] = *(const float4*)(kp + (long)r * C3 + c);
    }
    {
        // v: thread -> row r=t&63, two float4 chunks; conflict-free svT scatter
        const int r  = t & 63;
        const int pr = (r >> 3) * 8 + perm8(r & 7);
        #pragma unroll
        for (int it = 0; it < 2; ++it) {
            int c = ((t >> 6) * 2 + it) * 4;
            float4 v = *(const float4*)(vp + (long)r * C3 + c);
            svT[c+0][pr] = v.x; svT[c+1][pr] = v.y;
            svT[c+2][pr] = v.z; svT[c+3][pr] = v.w;
        }
    }
    __syncthreads();

    // ---- Phase 1b: per-row normalize + scale + RoPE, rewrite permuted ----
    if (t < 128) {
        const int r = t & 63;
        float* row = (t < 64) ? &sq[r][0] : &sk[r][0];
        float x[32];
        #pragma unroll
        for (int c4 = 0; c4 < 8; ++c4) *(float4*)&x[c4*4] = *(float4*)&row[c4*4];

        float ss = 0.f;
        #pragma unroll
        for (int d = 0; d < 32; ++d) ss += x[d] * x[d];
        float scale = 1.0f / fmaxf(sqrtf(ss), 1e-12f);
        if (t < 64)
            scale *= expf(fmaxf(logit_scale[h], LN100)) * 0.17677669529663687f;

        const float inv_tab[8] = {
            1.0f, 0.31622776601683794f, 0.1f, 0.03162277660168379f,
            0.01f, 0.0031622776601683794f, 0.001f, 0.00031622776601683794f };

        const int ih = r >> 3, iw = r & 7;
        float y[32];
        #pragma unroll
        for (int p = 0; p < 16; ++p) {
            const int d = 2 * p;
            const float pos = (p < 8) ? (float)ih : (float)iw;
            const float f = pos * inv_tab[p & 7];
            float sf, cf;
            sincosf(f, &sf, &cf);
            const float x0 = x[d] * scale, x1 = x[d + 1] * scale;
            y[d]     = x0 * cf - x1 * sf;
            y[d + 1] = x1 * cf + x0 * sf;
        }
        #pragma unroll
        for (int d = 0; d < 32; ++d)
            row[(d >> 3) * 8 + perm8(d & 7)] = y[d];
    }
    __syncthreads();

    // ---- Phase 2: scores S = q k^T (64x64x32), 3xTF32 ----
    {
        float c[2][2][4] = {};
        #pragma unroll
        for (int ks = 0; ks < 4; ++ks) {
            const int ko = ks * 8 + 2 * t4;
            unsigned ah[2][4], al[2][4], bh[2][2], bl[2][2];
            #pragma unroll
            for (int mt = 0; mt < 2; ++mt) {
                const int r0 = wm*32 + mt*16 + g;
                float2 xx = *(const float2*)&sq[r0    ][ko];
                float2 yy = *(const float2*)&sq[r0 + 8][ko];
                float a0 = xx.x, a2 = xx.y, a1 = yy.x, a3 = yy.y;
                ah[mt][0]=f2tf32(a0); al[mt][0]=f2tf32(a0 - __uint_as_float(ah[mt][0]));
                ah[mt][1]=f2tf32(a1); al[mt][1]=f2tf32(a1 - __uint_as_float(ah[mt][1]));
                ah[mt][2]=f2tf32(a2); al[mt][2]=f2tf32(a2 - __uint_as_float(ah[mt][2]));
                ah[mt][3]=f2tf32(a3); al[mt][3]=f2tf32(a3 - __uint_as_float(ah[mt][3]));
            }
            #pragma unroll
            for (int nt = 0; nt < 2; ++nt) {
                const int c0 = wn*16 + nt*8 + g;
                float2 bv = *(const float2*)&sk[c0][ko];
                bh[nt][0]=f2tf32(bv.x); bl[nt][0]=f2tf32(bv.x - __uint_as_float(bh[nt][0]));
                bh[nt][1]=f2tf32(bv.y); bl[nt][1]=f2tf32(bv.y - __uint_as_float(bh[nt][1]));
            }
            #pragma unroll
            for (int mt = 0; mt < 2; ++mt)
                #pragma unroll
                for (int nt = 0; nt < 2; ++nt) {
                    mma_tf32(c[mt][nt], ah[mt], bh[nt]);
                    mma_tf32(c[mt][nt], al[mt], bh[nt]);
                    mma_tf32(c[mt][nt], ah[mt], bl[nt]);
                }
        }
        const int p0 = perm8(2 * t4), p1 = perm8(2 * t4 + 1);
        #pragma unroll
        for (int mt = 0; mt < 2; ++mt) {
            const int r0 = wm*32 + mt*16 + g;
            #pragma unroll
            for (int nt = 0; nt < 2; ++nt) {
                const int cg = wn*16 + nt*8;
                sp[r0    ][cg + p0] = c[mt][nt][0];
                sp[r0    ][cg + p1] = c[mt][nt][1];
                sp[r0 + 8][cg + p0] = c[mt][nt][2];
                sp[r0 + 8][cg + p1] = c[mt][nt][3];
            }
        }
    }
    __syncthreads();

    // ---- Phase 3: softmax over rows (perm order irrelevant) ----
    {
        const int r  = t >> 2;
        const int cb = (t & 3) * 16;
        float sc[16];
        #pragma unroll
        for (int q4 = 0; q4 < 4; ++q4)
            *(float4*)&sc[q4*4] = *(const float4*)&sp[r][cb + q4*4];
        float mx = sc[0];
        #pragma unroll
        for (int i = 1; i < 16; ++i) mx = fmaxf(mx, sc[i]);
        mx = fmaxf(mx, __shfl_xor_sync(0xffffffff, mx, 1));
        mx = fmaxf(mx, __shfl_xor_sync(0xffffffff, mx, 2));
        float sum = 0.f;
        #pragma unroll
        for (int i = 0; i < 16; ++i) { sc[i] = __expf(sc[i] - mx); sum += sc[i]; }
        sum += __shfl_xor_sync(0xffffffff, sum, 1);
        sum += __shfl_xor_sync(0xffffffff, sum, 2);
        const float rinv = 1.0f / sum;
        #pragma unroll
        for (int i = 0; i < 16; ++i) sc[i] *= rinv;
        #pragma unroll
        for (int q4 = 0; q4 < 4; ++q4)
            *(float4*)&sp[r][cb + q4*4] = *(float4*)&sc[q4*4];
    }
    __syncthreads();

    // ---- Phase 4: O = P V (64x32x64), 3xTF32 ----
    {
        float c[2][4] = {};
        #pragma unroll
        for (int ks = 0; ks < 8; ++ks) {
            const int ko = ks * 8 + 2 * t4;
            unsigned ah[2][4], al[2][4], bh[2], bl[2];
            #pragma unroll
            for (int mt = 0; mt < 2; ++mt) {
                const int r0 = wm*32 + mt*16 + g;
                float2 xx = *(const float2*)&sp[r0    ][ko];
                float2 yy = *(const float2*)&sp[r0 + 8][ko];
                float a0 = xx.x, a2 = xx.y, a1 = yy.x, a3 = yy.y;
                ah[mt][0]=f2tf32(a0); al[mt][0]=f2tf32(a0 - __uint_as_float(ah[mt][0]));
                ah[mt][1]=f2tf32(a1); al[mt][1]=f2tf32(a1 - __uint_as_float(ah[mt][1]));
                ah[mt][2]=f2tf32(a2); al[mt][2]=f2tf32(a2 - __uint_as_float(ah[mt][2]));
                ah[mt][3]=f2tf32(a3); al[mt][3]=f2tf32(a3 - __uint_as_float(ah[mt][3]));
            }
            {
                const int c0 = wn*8 + g;
                float2 bv = *(const float2*)&svT[c0][ko];
                bh[0]=f2tf32(bv.x); bl[0]=f2tf32(bv.x - __uint_as_float(bh[0]));
                bh[1]=f2tf32(bv.y); bl[1]=f2tf32(bv.y - __uint_as_float(bh[1]));
            }
            #pragma unroll
            for (int mt = 0; mt < 2; ++mt) {
                mma_tf32(c[mt], ah[mt], bh);
                mma_tf32(c[mt], al[mt], bh);
                mma_tf32(c[mt], ah[mt], bl);
            }
        }
        const int col = wn*8 + 2*t4 + h*HD;
        #pragma unroll
        for (int mt = 0; mt < 2; ++mt) {
            const int r0 = wm*32 + mt*16 + g;
            float2 o0 = make_float2(c[mt][0], c[mt][1]);
            float2 o1 = make_float2(c[mt][2], c[mt][3]);
            *(float2*)&out[(rowm + r0    ) * DIM + col] = o0;
            *(float2*)&out[(rowm + r0 + 8) * DIM + col] = o1;
        }
    }
}

// ---------------------------------------------------------------------------
extern "C" void kernel_launch(void* const* d_in, const int* in_sizes, int n_in,
                              void* d_out, int out_size)
{
    const float* x           = (const float*)d_in[0];
    const float* qkv_weight  = (const float*)d_in[1];
    const float* q_bias      = (const float*)d_in[2];
    const float* v_bias      = (const float*)d_in[3];
    const float* logit_scale = (const float*)d_in[4];
    const float* proj_weight = (const float*)d_in[5];
    const float* proj_bias   = (const float*)d_in[6];
    float* outp = (float*)d_out;

    float* qkv; cudaGetSymbolAddress((void**)&qkv, g_qkv);
    float* att; cudaGetSymbolAddress((void**)&att, g_att);

    // 1) qkv = x @ Wqkv^T + [q_bias | 0 | v_bias]   (32768 x 1536 x 512)
    mma_gemm<C3, DIM, 0><<<dim3(C3/128, MROWS/128), 256>>>(
        x, qkv_weight, q_bias, v_bias, qkv);

    // 2) windowed cosine attention + RoPE (tensor cores, 3xTF32)
    attn_kernel<<<dim3(NW, HEADS, BATCH), 256>>>(logit_scale, att);

    // 3) out = att @ Wproj^T + proj_bias            (32768 x 512 x 512)
    mma_gemm<DIM, DIM, 1><<<dim3(DIM/128, MROWS/128), 256>>>(
        att, proj_weight, proj_bias, nullptr, outp);
}

// round 4
// speedup vs baseline: 3.6501x; 1.1360x over previous
#include <cuda_runtime.h>
#include <cuda_bf16.h>
#include <cstdint>

// Problem constants
#define BATCH   8
#define NW      64
#define NTOK    64          // WH*WW
#define DIM     512
#define HEADS   16
#define HD      32
#define C3      1536        // 3*DIM
#define MROWS   (BATCH*NW*NTOK)   // 32768
#define LN100   4.605170185988092f

// Scratch (allocation-free rule: __device__ globals)
__device__ float g_qkv[(long)MROWS * C3];     // 192 MB
__device__ float g_att[(long)MROWS * DIM];    // 64 MB

__device__ __forceinline__ unsigned f2tf32(float x) {
    unsigned u;
    asm("cvt.rna.tf32.f32 %0, %1;" : "=r"(u) : "f"(x));
    return u;
}

__device__ __forceinline__ void mma_tf32(float c[4], const unsigned a[4], const unsigned b[2]) {
    asm volatile(
        "mma.sync.aligned.m16n8k8.row.col.f32.tf32.tf32.f32 "
        "{%0,%1,%2,%3}, {%4,%5,%6,%7}, {%8,%9}, {%0,%1,%2,%3};"
        : "+f"(c[0]), "+f"(c[1]), "+f"(c[2]), "+f"(c[3])
        : "r"(a[0]), "r"(a[1]), "r"(a[2]), "r"(a[3]), "r"(b[0]), "r"(b[1]));
}

// within an 8-wide k-group, put (k, k+4) adjacent: kk -> ((kk&3)<<1)|(kk>>2)
__device__ __forceinline__ int perm8(int kk) { return ((kk & 3) << 1) | (kk >> 2); }

// ---------------------------------------------------------------------------
// TF32 tensor-core GEMM: C[m,n] = sum_k A[m,k] * W[n,k] + bias(n)
// CTA 128x128, BK=32, 256 threads = 8 warps (2M x 4N), warp tile 64x32.
// Smem rows hold k in pair-permuted order so fragment loads are LDS.64.
// __launch_bounds__(256,2) caps regs at 128 -> 2 CTAs/SM (occupancy fix).
// ---------------------------------------------------------------------------
template<int N, int K, int MODE>
__global__ __launch_bounds__(256, 2) void mma_gemm(
    const float* __restrict__ A, const float* __restrict__ W,
    const float* __restrict__ b0, const float* __restrict__ b1,
    float* __restrict__ C)
{
    __shared__ unsigned As[128][40];   // [m][perm(k)] tf32 bits
    __shared__ unsigned Bs[128][40];   // [n][perm(k)]

    const int t    = threadIdx.x;
    const int warp = t >> 5;
    const int lane = t & 31;
    const int g    = lane >> 2;
    const int t4   = lane & 3;
    const int wm   = warp >> 2;
    const int wn   = warp & 3;

    const int rowBase = blockIdx.y * 128;
    const int colBase = blockIdx.x * 128;

    // staging: thread t covers row (p*32 + t>>3), k-group (t&7)>>1, half (t&7)&1
    const int ldr  = t >> 3;
    const int j    = t & 7;
    const int g8   = j >> 1;
    const int kk0  = (j & 1) * 2;
    const int kOff = g8 * 8 + kk0;        // gmem k base (loads kOff,kOff+1 and +4,+5)
    const int sOff = g8 * 8 + kk0 * 2;    // smem word base (4 perm-contiguous slots)

    float acc[4][4][4] = {};
    float2 aU[4], aW[4], bU[4], bW[4];

    // prologue stage kt=0
    #pragma unroll
    for (int p = 0; p < 4; ++p) {
        const float* ap = A + (long)(rowBase + p*32 + ldr) * K + kOff;
        aU[p] = *(const float2*)ap;  aW[p] = *(const float2*)(ap + 4);
        const float* bp = W + (long)(colBase + p*32 + ldr) * K + kOff;
        bU[p] = *(const float2*)bp;  bW[p] = *(const float2*)(bp + 4);
    }
    #pragma unroll
    for (int p = 0; p < 4; ++p) {
        uint4 av = make_uint4(f2tf32(aU[p].x), f2tf32(aW[p].x), f2tf32(aU[p].y), f2tf32(aW[p].y));
        *(uint4*)&As[p*32 + ldr][sOff] = av;
        uint4 bv = make_uint4(f2tf32(bU[p].x), f2tf32(bW[p].x), f2tf32(bU[p].y), f2tf32(bW[p].y));
        *(uint4*)&Bs[p*32 + ldr][sOff] = bv;
    }
    __syncthreads();

    for (int kt = 0; kt < K; kt += 32) {
        const bool more = (kt + 32) < K;
        if (more) {
            #pragma unroll
            for (int p = 0; p < 4; ++p) {
                const float* ap = A + (long)(rowBase + p*32 + ldr) * K + kt + 32 + kOff;
                aU[p] = *(const float2*)ap;  aW[p] = *(const float2*)(ap + 4);
                const float* bp = W + (long)(colBase + p*32 + ldr) * K + kt + 32 + kOff;
                bU[p] = *(const float2*)bp;  bW[p] = *(const float2*)(bp + 4);
            }
        }

        #pragma unroll
        for (int ks = 0; ks < 4; ++ks) {
            const int ko = ks * 8 + 2 * t4;
            unsigned af[4][4], bf[4][2];
            #pragma unroll
            for (int mt = 0; mt < 4; ++mt) {
                const int r0 = wm*64 + mt*16 + g;
                uint2 x = *(const uint2*)&As[r0    ][ko];
                uint2 y = *(const uint2*)&As[r0 + 8][ko];
                af[mt][0] = x.x; af[mt][2] = x.y;
                af[mt][1] = y.x; af[mt][3] = y.y;
            }
            #pragma unroll
            for (int nt = 0; nt < 4; ++nt) {
                const int c0 = wn*32 + nt*8 + g;
                uint2 bb = *(const uint2*)&Bs[c0][ko];
                bf[nt][0] = bb.x; bf[nt][1] = bb.y;
            }
            #pragma unroll
            for (int mt = 0; mt < 4; ++mt)
                #pragma unroll
                for (int nt = 0; nt < 4; ++nt)
                    mma_tf32(acc[mt][nt], af[mt], bf[nt]);
        }

        if (more) {
            __syncthreads();
            #pragma unroll
            for (int p = 0; p < 4; ++p) {
                uint4 av = make_uint4(f2tf32(aU[p].x), f2tf32(aW[p].x), f2tf32(aU[p].y), f2tf32(aW[p].y));
                *(uint4*)&As[p*32 + ldr][sOff] = av;
                uint4 bv = make_uint4(f2tf32(bU[p].x), f2tf32(bW[p].x), f2tf32(bU[p].y), f2tf32(bW[p].y));
                *(uint4*)&Bs[p*32 + ldr][sOff] = bv;
            }
            __syncthreads();
        }
    }

    // epilogue with bias
    #pragma unroll
    for (int mt = 0; mt < 4; ++mt) {
        #pragma unroll
        for (int nt = 0; nt < 4; ++nt) {
            const int row0 = rowBase + wm*64 + mt*16 + g;
            const int col0 = colBase + wn*32 + nt*8 + t4*2;
            float bias0, bias1;
            if (MODE == 0) {
                bias0 = (col0 < 512) ? b0[col0] : ((col0 < 1024) ? 0.0f : b1[col0 - 1024]);
                const int c1 = col0 + 1;
                bias1 = (c1 < 512) ? b0[c1] : ((c1 < 1024) ? 0.0f : b1[c1 - 1024]);
            } else {
                bias0 = b0[col0];
                bias1 = b0[col0 + 1];
            }
            C[(long)row0 * N + col0    ] = acc[mt][nt][0] + bias0;
            C[(long)row0 * N + col0 + 1] = acc[mt][nt][1] + bias1;
            C[(long)(row0+8) * N + col0    ] = acc[mt][nt][2] + bias0;
            C[(long)(row0+8) * N + col0 + 1] = acc[mt][nt][3] + bias1;
        }
    }
}

// ---------------------------------------------------------------------------
// Per-window cosine attention with axial RoPE — tensor-core (3xTF32 = ~fp32).
// Grid: (NW, HEADS, BATCH), 256 threads = 8 warps (2M x 4N).
// ---------------------------------------------------------------------------
__global__ __launch_bounds__(256, 2) void attn_kernel(
    const float* __restrict__ logit_scale, float* __restrict__ out)
{
    __shared__ float sq [64][40];   // q rows, k-perm layout (after phase 1b)
    __shared__ float sk [64][40];   // k rows, k-perm layout
    __shared__ float svT[32][72];   // V transposed: [d][perm(key)]
    __shared__ float sp [64][72];   // scores/probs: [q][perm(key)]

    const int w = blockIdx.x, h = blockIdx.y, b = blockIdx.z;
    const int t    = threadIdx.x;
    const int warp = t >> 5;
    const int lane = t & 31;
    const int g    = lane >> 2;
    const int t4   = lane & 3;
    const int wm   = warp >> 2;
    const int wn   = warp & 3;

    const long rowm = (long)(b * NW + w) * NTOK;
    const float* qp = g_qkv + rowm * C3 + h * HD;
    const float* kp = qp + 512;
    const float* vp = qp + 1024;

    // ---- Phase 1a: load q,k raw row-major; V transposed+permuted ----
    #pragma unroll
    for (int it = 0; it < 2; ++it) {
        int idx = t + it * 256;
        int r = idx >> 3, c = (idx & 7) * 4;
        *(float4*)&sq[r][c] = *(const float4*)(qp + (long)r * C3 + c);
        *(float4*)&sk[r][c] = *(const float4*)(kp + (long)r * C3 + c);
    }
    {
        // v: thread -> row r=t&63, two float4 chunks; conflict-free svT scatter
        const int r  = t & 63;
        const int pr = (r >> 3) * 8 + perm8(r & 7);
        #pragma unroll
        for (int it = 0; it < 2; ++it) {
            int c = ((t >> 6) * 2 + it) * 4;
            float4 v = *(const float4*)(vp + (long)r * C3 + c);
            svT[c+0][pr] = v.x; svT[c+1][pr] = v.y;
            svT[c+2][pr] = v.z; svT[c+3][pr] = v.w;
        }
    }
    __syncthreads();

    // ---- Phase 1b: per-row normalize + scale + RoPE, rewrite permuted ----
    if (t < 128) {
        const int r = t & 63;
        float* row = (t < 64) ? &sq[r][0] : &sk[r][0];
        float x[32];
        #pragma unroll
        for (int c4 = 0; c4 < 8; ++c4) *(float4*)&x[c4*4] = *(float4*)&row[c4*4];

        float ss = 0.f;
        #pragma unroll
        for (int d = 0; d < 32; ++d) ss += x[d] * x[d];
        float scale = 1.0f / fmaxf(sqrtf(ss), 1e-12f);
        if (t < 64)
            scale *= expf(fmaxf(logit_scale[h], LN100)) * 0.17677669529663687f;

        const float inv_tab[8] = {
            1.0f, 0.31622776601683794f, 0.1f, 0.03162277660168379f,
            0.01f, 0.0031622776601683794f, 0.001f, 0.00031622776601683794f };

        const int ih = r >> 3, iw = r & 7;
        float y[32];
        #pragma unroll
        for (int p = 0; p < 16; ++p) {
            const int d = 2 * p;
            const float pos = (p < 8) ? (float)ih : (float)iw;
            const float f = pos * inv_tab[p & 7];
            float sf, cf;
            sincosf(f, &sf, &cf);
            const float x0 = x[d] * scale, x1 = x[d + 1] * scale;
            y[d]     = x0 * cf - x1 * sf;
            y[d + 1] = x1 * cf + x0 * sf;
        }
        #pragma unroll
        for (int d = 0; d < 32; ++d)
            row[(d >> 3) * 8 + perm8(d & 7)] = y[d];
    }
    __syncthreads();

    // ---- Phase 2: scores S = q k^T (64x64x32), 3xTF32 ----
    {
        float c[2][2][4] = {};
        #pragma unroll
        for (int ks = 0; ks < 4; ++ks) {
            const int ko = ks * 8 + 2 * t4;
            unsigned ah[2][4], al[2][4], bh[2][2], bl[2][2];
            #pragma unroll
            for (int mt = 0; mt < 2; ++mt) {
                const int r0 = wm*32 + mt*16 + g;
                float2 xx = *(const float2*)&sq[r0    ][ko];
                float2 yy = *(const float2*)&sq[r0 + 8][ko];
                float a0 = xx.x, a2 = xx.y, a1 = yy.x, a3 = yy.y;
                ah[mt][0]=f2tf32(a0); al[mt][0]=f2tf32(a0 - __uint_as_float(ah[mt][0]));
                ah[mt][1]=f2tf32(a1); al[mt][1]=f2tf32(a1 - __uint_as_float(ah[mt][1]));
                ah[mt][2]=f2tf32(a2); al[mt][2]=f2tf32(a2 - __uint_as_float(ah[mt][2]));
                ah[mt][3]=f2tf32(a3); al[mt][3]=f2tf32(a3 - __uint_as_float(ah[mt][3]));
            }
            #pragma unroll
            for (int nt = 0; nt < 2; ++nt) {
                const int c0 = wn*16 + nt*8 + g;
                float2 bv = *(const float2*)&sk[c0][ko];
                bh[nt][0]=f2tf32(bv.x); bl[nt][0]=f2tf32(bv.x - __uint_as_float(bh[nt][0]));
                bh[nt][1]=f2tf32(bv.y); bl[nt][1]=f2tf32(bv.y - __uint_as_float(bh[nt][1]));
            }
            #pragma unroll
            for (int mt = 0; mt < 2; ++mt)
                #pragma unroll
                for (int nt = 0; nt < 2; ++nt) {
                    mma_tf32(c[mt][nt], ah[mt], bh[nt]);
                    mma_tf32(c[mt][nt], al[mt], bh[nt]);
                    mma_tf32(c[mt][nt], ah[mt], bl[nt]);
                }
        }
        const int p0 = perm8(2 * t4), p1 = perm8(2 * t4 + 1);
        #pragma unroll
        for (int mt = 0; mt < 2; ++mt) {
            const int r0 = wm*32 + mt*16 + g;
            #pragma unroll
            for (int nt = 0; nt < 2; ++nt) {
                const int cg = wn*16 + nt*8;
                sp[r0    ][cg + p0] = c[mt][nt][0];
                sp[r0    ][cg + p1] = c[mt][nt][1];
                sp[r0 + 8][cg + p0] = c[mt][nt][2];
                sp[r0 + 8][cg + p1] = c[mt][nt][3];
            }
        }
    }
    __syncthreads();

    // ---- Phase 3: softmax over rows (perm order irrelevant) ----
    {
        const int r  = t >> 2;
        const int cb = (t & 3) * 16;
        float sc[16];
        #pragma unroll
        for (int q4 = 0; q4 < 4; ++q4)
            *(float4*)&sc[q4*4] = *(const float4*)&sp[r][cb + q4*4];
        float mx = sc[0];
        #pragma unroll
        for (int i = 1; i < 16; ++i) mx = fmaxf(mx, sc[i]);
        mx = fmaxf(mx, __shfl_xor_sync(0xffffffff, mx, 1));
        mx = fmaxf(mx, __shfl_xor_sync(0xffffffff, mx, 2));
        float sum = 0.f;
        #pragma unroll
        for (int i = 0; i < 16; ++i) { sc[i] = __expf(sc[i] - mx); sum += sc[i]; }
        sum += __shfl_xor_sync(0xffffffff, sum, 1);
        sum += __shfl_xor_sync(0xffffffff, sum, 2);
        const float rinv = 1.0f / sum;
        #pragma unroll
        for (int i = 0; i < 16; ++i) sc[i] *= rinv;
        #pragma unroll
        for (int q4 = 0; q4 < 4; ++q4)
            *(float4*)&sp[r][cb + q4*4] = *(float4*)&sc[q4*4];
    }
    __syncthreads();

    // ---- Phase 4: O = P V (64x32x64), 3xTF32 ----
    {
        float c[2][4] = {};
        #pragma unroll
        for (int ks = 0; ks < 8; ++ks) {
            const int ko = ks * 8 + 2 * t4;
            unsigned ah[2][4], al[2][4], bh[2], bl[2];
            #pragma unroll
            for (int mt = 0; mt < 2; ++mt) {
                const int r0 = wm*32 + mt*16 + g;
                float2 xx = *(const float2*)&sp[r0    ][ko];
                float2 yy = *(const float2*)&sp[r0 + 8][ko];
                float a0 = xx.x, a2 = xx.y, a1 = yy.x, a3 = yy.y;
                ah[mt][0]=f2tf32(a0); al[mt][0]=f2tf32(a0 - __uint_as_float(ah[mt][0]));
                ah[mt][1]=f2tf32(a1); al[mt][1]=f2tf32(a1 - __uint_as_float(ah[mt][1]));
                ah[mt][2]=f2tf32(a2); al[mt][2]=f2tf32(a2 - __uint_as_float(ah[mt][2]));
                ah[mt][3]=f2tf32(a3); al[mt][3]=f2tf32(a3 - __uint_as_float(ah[mt][3]));
            }
            {
                const int c0 = wn*8 + g;
                float2 bv = *(const float2*)&svT[c0][ko];
                bh[0]=f2tf32(bv.x); bl[0]=f2tf32(bv.x - __uint_as_float(bh[0]));
                bh[1]=f2tf32(bv.y); bl[1]=f2tf32(bv.y - __uint_as_float(bh[1]));
            }
            #pragma unroll
            for (int mt = 0; mt < 2; ++mt) {
                mma_tf32(c[mt], ah[mt], bh);
                mma_tf32(c[mt], al[mt], bh);
                mma_tf32(c[mt], ah[mt], bl);
            }
        }
        const int col = wn*8 + 2*t4 + h*HD;
        #pragma unroll
        for (int mt = 0; mt < 2; ++mt) {
            const int r0 = wm*32 + mt*16 + g;
            float2 o0 = make_float2(c[mt][0], c[mt][1]);
            float2 o1 = make_float2(c[mt][2], c[mt][3]);
            *(float2*)&out[(rowm + r0    ) * DIM + col] = o0;
            *(float2*)&out[(rowm + r0 + 8) * DIM + col] = o1;
        }
    }
}

// ---------------------------------------------------------------------------
extern "C" void kernel_launch(void* const* d_in, const int* in_sizes, int n_in,
                              void* d_out, int out_size)
{
    const float* x           = (const float*)d_in[0];
    const float* qkv_weight  = (const float*)d_in[1];
    const float* q_bias      = (const float*)d_in[2];
    const float* v_bias      = (const float*)d_in[3];
    const float* logit_scale = (const float*)d_in[4];
    const float* proj_weight = (const float*)d_in[5];
    const float* proj_bias   = (const float*)d_in[6];
    float* outp = (float*)d_out;

    float* qkv; cudaGetSymbolAddress((void**)&qkv, g_qkv);
    float* att; cudaGetSymbolAddress((void**)&att, g_att);

    // 1) qkv = x @ Wqkv^T + [q_bias | 0 | v_bias]   (32768 x 1536 x 512)
    mma_gemm<C3, DIM, 0><<<dim3(C3/128, MROWS/128), 256>>>(
        x, qkv_weight, q_bias, v_bias, qkv);

    // 2) windowed cosine attention + RoPE (tensor cores, 3xTF32)
    attn_kernel<<<dim3(NW, HEADS, BATCH), 256>>>(logit_scale, att);

    // 3) out = att @ Wproj^T + proj_bias            (32768 x 512 x 512)
    mma_gemm<DIM, DIM, 1><<<dim3(DIM/128, MROWS/128), 256>>>(
        att, proj_weight, proj_bias, nullptr, outp);
}